// round 14
// baseline (speedup 1.0000x reference)
#include <cuda_runtime.h>
#include <math.h>

#define FULLMASK 0xffffffffu

constexpr int N_ = 50000;
constexpr int E_ = 400000;
constexpr int R_ = 4;
constexpr int HC_ = 128;   // H*C
constexpr int D_ = 64;     // IN == HID
constexpr int L_ = 2;
constexpr int K1_ = D_ + R_ * HC_;  // 576
constexpr int SEG_ = R_ * N_;       // 200000 segments
constexpr int CAP_ = 32;            // ELL capacity (deg ~ Poisson(4); P(>=32) ~ 1e-19)
constexpr int LOGITS_BLKS = (N_ + 63) / 64;        // 782
constexpr int ELL_BLKS = (E_ + 255) / 256;         // 1563

// ---------------- scratch (device globals) ---------------------------------
__device__ int g_ellcnt[SEG_];          // zero-init at load; re-zeroed by setup
__device__ int g_ell[CAP_][SEG_];       // transposed ELL adjacency

__device__ float g_es[R_][N_][2];       // per-node source logits, per head
__device__ float g_ed[R_][N_][2];       // per-node dest logits, per head
__device__ float g_aggx[R_][N_][HC_];   // normalized alpha-weighted x, [h*64+k]
__device__ float g_hbuf[N_][D_];        // inter-layer features
__device__ float g_va[L_][2][R_][2][D_];  // folded W@a_{src,dst}
__device__ float g_W1f[L_][K1_][D_];    // MLP W1 with GAT W folded in
__device__ float g_b1f[L_][D_];         // b1 with gat_bias folded in

__device__ __forceinline__ float lrelu(float x) { return x > 0.f ? x : 0.2f * x; }

// packed 2xfp32 FMA (sm_100+): d = a*b + d elementwise on {lo,hi}
__device__ __forceinline__ void ffma2(unsigned long long& d,
                                      unsigned long long a, unsigned long long b) {
    asm("fma.rn.f32x2 %0, %1, %2, %3;" : "=l"(d) : "l"(a), "l"(b), "l"(d));
}
// duplicate a float into both halves of a packed f32x2
__device__ __forceinline__ unsigned long long packdup(float a) {
    unsigned long long d;
    unsigned int u = __float_as_uint(a);
    asm("mov.b64 %0, {%1, %1};" : "=l"(d) : "r"(u));
    return d;
}

// ================= merged one-time setup ====================================
__global__ __launch_bounds__(256) void setup_kernel(
    const float* __restrict__ gatW, const float* __restrict__ asrc,
    const float* __restrict__ adst, const float* __restrict__ W1,
    const float* __restrict__ b1, const float* __restrict__ gbias)
{
    __shared__ float Wt[64][65];   // [k][c]
    __shared__ float W1t[64][64];  // [c][j]
    int b = blockIdx.x;
    int tid = threadIdx.x;

    if (b == 0) {
#pragma unroll
        for (int it = 0; it < 4; it++) {
            int t = tid + it * 256;
            int k = t & 63;
            int h = (t >> 6) & 1;
            int r = (t >> 7) & 3;
            int l = t >> 9;
            const float* Wrow = gatW + (((size_t)(l * R_ + r) * 64 + k) * 128) + h * 64;
            const float* as = asrc + ((l * R_ + r) * 2 + h) * 64;
            const float* ad = adst + ((l * R_ + r) * 2 + h) * 64;
            float ss = 0.f, ds = 0.f;
#pragma unroll 16
            for (int c = 0; c < 64; c++) { ss += Wrow[c] * as[c]; ds += Wrow[c] * ad[c]; }
            g_va[l][0][r][h][k] = ss;
            g_va[l][1][r][h][k] = ds;
        }
    } else if (b <= L_) {
        int l = b - 1;
        for (int i = tid; i < 64 * 64 / 4; i += 256)
            ((float4*)&g_W1f[l][0][0])[i] = ((const float4*)&W1[(size_t)l * K1_ * 64])[i];
        if (tid < 64) {
            float bb = b1[l * 64 + tid];
            for (int row = 0; row < 512; row++) {
                int r = row >> 7, idx = row & 127;
                bb += gbias[(l * R_ + r) * HC_ + idx] *
                      W1[((size_t)l * K1_ + 64 + row) * 64 + tid];
            }
            g_b1f[l][tid] = bb;
        }
    } else if (b <= L_ + 16) {
        int sub = b - 3;
        int l = sub >> 3, r = (sub >> 1) & 3, h = sub & 1;
#pragma unroll
        for (int i = 0; i < 4; i++) {
            int s = tid + i * 256;
            int k = s >> 4, c4 = (s & 15) * 4;
            float4 wv = *(const float4*)&gatW[((size_t)(l * R_ + r) * 64 + k) * 128 + h * 64 + c4];
            Wt[k][c4] = wv.x; Wt[k][c4 + 1] = wv.y; Wt[k][c4 + 2] = wv.z; Wt[k][c4 + 3] = wv.w;
            int c = s >> 4, j4 = (s & 15) * 4;
            *(float4*)&W1t[c][j4] =
                *(const float4*)&W1[((size_t)l * K1_ + 64 + r * 128 + h * 64 + c) * 64 + j4];
        }
        __syncthreads();
        int j4 = (tid & 15) * 4;
        int kb = tid >> 4;
#pragma unroll
        for (int kk = 0; kk < 4; kk++) {
            int k = kb + kk * 16;
            float a0 = 0.f, a1 = 0.f, a2 = 0.f, a3 = 0.f;
#pragma unroll 16
            for (int c = 0; c < 64; c++) {
                float a = Wt[k][c];
                float4 wv = *(float4*)&W1t[c][j4];
                a0 += a * wv.x; a1 += a * wv.y; a2 += a * wv.z; a3 += a * wv.w;
            }
            *(float4*)&g_W1f[l][64 + r * 128 + h * 64 + k][j4] = make_float4(a0, a1, a2, a3);
        }
    } else {
        int i4 = (b - (L_ + 17)) * 256 + tid;
        if (i4 < SEG_ / 4) ((int4*)g_ellcnt)[i4] = make_int4(0, 0, 0, 0);
    }
}

// ================= logits body (device fn, shared by fused + standalone) ===
__device__ __forceinline__ void logits_body(const float* __restrict__ xcur,
                                            int layer, int blk)
{
    __shared__ float xs[64][68];    // stride 68: 16B-aligned float4 rows
    __shared__ float vas[16][68];
    int tid = threadIdx.x;
    int nb = blk * 64;
#pragma unroll
    for (int i = 0; i < 4; i++) {
        int s = tid + i * 256;
        int row = s >> 4, c4 = (s & 15) * 4;
        int n = nb + row;
        float4 v = (n < N_) ? *(const float4*)&xcur[(size_t)n * 64 + c4]
                            : make_float4(0.f, 0.f, 0.f, 0.f);
        xs[row][c4] = v.x; xs[row][c4 + 1] = v.y; xs[row][c4 + 2] = v.z; xs[row][c4 + 3] = v.w;
    }
    {
        int o = tid >> 4, c4 = (tid & 15) * 4;
        int which = o >> 3, oo = o & 7;
        int r = oo >> 1, h = oo & 1;
        float4 v = *(const float4*)&g_va[layer][which][r][h][c4];
        vas[o][c4] = v.x; vas[o][c4 + 1] = v.y; vas[o][c4 + 2] = v.z; vas[o][c4 + 3] = v.w;
    }
    __syncthreads();

    int o = tid & 15;
    int n0 = tid >> 4;
    float s0 = 0.f, s1 = 0.f, s2 = 0.f, s3 = 0.f;
#pragma unroll
    for (int k4 = 0; k4 < 64; k4 += 4) {
        float4 va = *(float4*)&vas[o][k4];
        float4 a = *(float4*)&xs[n0][k4];
        float4 b = *(float4*)&xs[n0 + 16][k4];
        float4 c = *(float4*)&xs[n0 + 32][k4];
        float4 d = *(float4*)&xs[n0 + 48][k4];
        s0 += a.x * va.x + a.y * va.y + a.z * va.z + a.w * va.w;
        s1 += b.x * va.x + b.y * va.y + b.z * va.z + b.w * va.w;
        s2 += c.x * va.x + c.y * va.y + c.z * va.z + c.w * va.w;
        s3 += d.x * va.x + d.y * va.y + d.z * va.z + d.w * va.w;
    }
    int which = o >> 3, oo = o & 7;
    int r = oo >> 1, h = oo & 1;
    float sv[4] = {s0, s1, s2, s3};
#pragma unroll
    for (int i = 0; i < 4; i++) {
        int n = nb + n0 + i * 16;
        if (n < N_) {
            if (which == 0) g_es[r][n][h] = sv[i];
            else            g_ed[r][n][h] = sv[i];
        }
    }
}

// ================= fused: logits layer 0 + ELL build =======================
__global__ __launch_bounds__(256) void logits_ell_kernel(
    const float* __restrict__ x, const int* __restrict__ ei,
    const float* __restrict__ ew)
{
    if (blockIdx.x < LOGITS_BLKS) {
        logits_body(x, 0, blockIdx.x);
    } else {
        int e = (blockIdx.x - LOGITS_BLKS) * 256 + threadIdx.x;
        if (e >= E_) return;
        float w = ew[e];
        if (w == 0.f) return;
        int s = ei[e], d = ei[E_ + e];
        int rf = (w > 0.f) ? 0 : 2;
        int seg0 = rf * N_ + d;
        int p0 = atomicAdd(&g_ellcnt[seg0], 1);
        if (p0 < CAP_) g_ell[p0][seg0] = s;
        int seg1 = (rf + 1) * N_ + s;
        int p1 = atomicAdd(&g_ellcnt[seg1], 1);
        if (p1 < CAP_) g_ell[p1][seg1] = d;
    }
}

// standalone logits for layer 1
__global__ __launch_bounds__(256) void logits_kernel(int layer)
{
    logits_body(&g_hbuf[0][0], layer, blockIdx.x);
}

// ================= per-layer: ELL softmax-aggregate (v5) ===================
__global__ __launch_bounds__(256) void agg_kernel(const float* __restrict__ xin, int layer)
{
    const float* xcur = layer ? &g_hbuf[0][0] : xin;
    int warp = (blockIdx.x * 256 + threadIdx.x) >> 5;
    int lane = threadIdx.x & 31;
    int li = lane & 15;
    int seg = warp * 2 + (lane >> 4);   // SEG_ % 2 == 0
    if (seg >= SEG_) return;
    int r = seg / N_;
    int n = seg - r * N_;

    int deg = __ldg(&g_ellcnt[seg]);
    deg = deg < CAP_ ? deg : CAP_;

    float2 ed2 = *(const float2*)&g_ed[r][n][0];
    float2 es2 = *(const float2*)&g_es[r][n][0];
    float p0 = __expf(lrelu(es2.x + ed2.x));   // self loop, head 0
    float p1 = __expf(lrelu(es2.y + ed2.y));   // self loop, head 1
    float4 xv = *(const float4*)&xcur[(size_t)n * 64 + li * 4];
    float den0 = p0, den1 = p1;
    float4 A0 = make_float4(p0 * xv.x, p0 * xv.y, p0 * xv.z, p0 * xv.w);
    float4 A1 = make_float4(p1 * xv.x, p1 * xv.y, p1 * xv.z, p1 * xv.w);

    int dmax = deg;
#pragma unroll
    for (int o = 16; o; o >>= 1) {
        int y = __shfl_xor_sync(FULLMASK, dmax, o);
        dmax = dmax > y ? dmax : y;
    }
#pragma unroll 4
    for (int it = 0; it < dmax; it++) {
        int slot = it < deg ? it : 0;          // slot 0 always valid (masked)
        float msk = it < deg ? 1.f : 0.f;
        int src = __ldg(&g_ell[slot][seg]);
        float2 e2 = *(const float2*)&g_es[r][src][0];
        float pe0 = msk * __expf(lrelu(e2.x + ed2.x));
        float pe1 = msk * __expf(lrelu(e2.y + ed2.y));
        den0 += pe0; den1 += pe1;
        float4 sv = *(const float4*)&xcur[(size_t)src * 64 + li * 4];
        A0.x += pe0 * sv.x; A0.y += pe0 * sv.y; A0.z += pe0 * sv.z; A0.w += pe0 * sv.w;
        A1.x += pe1 * sv.x; A1.y += pe1 * sv.y; A1.z += pe1 * sv.z; A1.w += pe1 * sv.w;
    }
    float i0 = 1.f / den0, i1 = 1.f / den1;
    *(float4*)&g_aggx[r][n][li * 4] =
        make_float4(A0.x * i0, A0.y * i0, A0.z * i0, A0.w * i0);
    *(float4*)&g_aggx[r][n][64 + li * 4] =
        make_float4(A1.x * i1, A1.y * i1, A1.z * i1, A1.w * i1);
}

// ================= fused MLP + residual + LayerNorm (FFMA2 v3) =============
// 256 threads (8 warps), tile 128 rows x 64 cols; per-thread 4 rows x 8 cols.
// Halved per-thread state vs v2 -> 2+ blocks/SM (occupancy fix).
constexpr int APAD2 = 132;   // 132*4 = 528 B, 16B-aligned rows
constexpr int BPAD2 = 72;    // 72*4 = 288 B, 16B-aligned rows

__global__ __launch_bounds__(256, 2) void mlp_kernel(
    const float* __restrict__ xin,
    const float* __restrict__ W2, const float* __restrict__ b2,
    const float* __restrict__ lng, const float* __restrict__ lnb,
    float* __restrict__ dout, int layer)
{
    __shared__ float Ast[32 * APAD2];   // 16896 B, [kk][row]
    __shared__ float Bs[32 * BPAD2];    // 9216 B,  [kk][col]
    __shared__ float b1s[64], b2s[64], gs[64], bs2[64];

    int tid = threadIdx.x;
    const float* hin = layer ? &g_hbuf[0][0] : xin;
    float* hout = (layer == L_ - 1) ? dout : &g_hbuf[0][0];

    if (tid < 64) {
        b1s[tid] = g_b1f[layer][tid];
        b2s[tid] = b2[layer * 64 + tid];
        gs[tid]  = lng[layer * 64 + tid];
        bs2[tid] = lnb[layer * 64 + tid];
    }

    int nb = blockIdx.x * 128;
    int lane = tid & 31, warp = tid >> 5;
    int tn = (((lane >> 3) & 3) << 1) | (lane & 1);   // 0..7 col group
    int tmw = (lane >> 1) & 3;
    int tm = warp * 4 + tmw;                           // 0..31 row group
    int rb = tm * 4;                                   // 4 rows per thread
    int cb = tn * 8;                                   // 8 cols per thread

    unsigned long long acc2[4][4];
#pragma unroll
    for (int i = 0; i < 4; i++)
#pragma unroll
        for (int p = 0; p < 4; p++) acc2[i][p] = 0ull;

    const float* W1l = &g_W1f[layer][0][0];

    for (int kt = 0; kt < 18; kt++) {
        const float* src; int stride, off;
        if (kt < 2) { src = hin; stride = 64; off = kt * 32; }
        else {
            int k0 = kt * 32 - 64;
            int rr = k0 >> 7; off = k0 & 127;
            src = &g_aggx[rr][0][0]; stride = 128;
        }
        __syncthreads();
        // A tile, transposed: 128 rows x 32 k (1024 float4 slots, 4 per thread)
#pragma unroll
        for (int i = 0; i < 4; i++) {
            int slot = tid + i * 256;
            int row = slot >> 3, c4 = (slot & 7) * 4;
            int n = nb + row;
            float4 v = make_float4(0.f, 0.f, 0.f, 0.f);
            if (n < N_) v = *(const float4*)&src[(size_t)n * stride + off + c4];
            Ast[(c4 + 0) * APAD2 + row] = v.x;
            Ast[(c4 + 1) * APAD2 + row] = v.y;
            Ast[(c4 + 2) * APAD2 + row] = v.z;
            Ast[(c4 + 3) * APAD2 + row] = v.w;
        }
        // B tile: 32 kk x 64 cols (512 float4 slots, 2 per thread)
#pragma unroll
        for (int i = 0; i < 2; i++) {
            int slot = tid + i * 256;
            int kk = slot >> 4, f4 = (slot & 15) * 4;
            *(float4*)&Bs[kk * BPAD2 + f4] = *(const float4*)&W1l[(kt * 32 + kk) * 64 + f4];
        }
        __syncthreads();
#pragma unroll 4
        for (int kk = 0; kk < 32; kk++) {
            float4 a0 = *(float4*)&Ast[kk * APAD2 + rb];
            const unsigned long long* bp = (const unsigned long long*)&Bs[kk * BPAD2 + cb];
            unsigned long long b0 = bp[0], b1r = bp[1], b2r = bp[2], b3 = bp[3];
            unsigned long long ad[4];
            ad[0] = packdup(a0.x); ad[1] = packdup(a0.y);
            ad[2] = packdup(a0.z); ad[3] = packdup(a0.w);
#pragma unroll
            for (int i = 0; i < 4; i++) {
                ffma2(acc2[i][0], ad[i], b0);
                ffma2(acc2[i][1], ad[i], b1r);
                ffma2(acc2[i][2], ad[i], b2r);
                ffma2(acc2[i][3], ad[i], b3);
            }
        }
    }

    // unpack + bias + tanh -> t[4 rows][8 cols]
    float t[4][8];
#pragma unroll
    for (int i = 0; i < 4; i++)
#pragma unroll
        for (int p = 0; p < 4; p++) {
            float lo = __uint_as_float((unsigned)(acc2[i][p] & 0xffffffffull));
            float hi = __uint_as_float((unsigned)(acc2[i][p] >> 32));
            t[i][2 * p]     = tanhf(lo + b1s[cb + 2 * p]);
            t[i][2 * p + 1] = tanhf(hi + b1s[cb + 2 * p + 1]);
        }

    // GEMM2 in two k-halves through the same smem
    const float* W2l = W2 + (size_t)layer * 64 * 64;
    unsigned long long z2[4][4];
#pragma unroll
    for (int i = 0; i < 4; i++)
#pragma unroll
        for (int p = 0; p < 4; p++) z2[i][p] = 0ull;

    for (int half = 0; half < 2; half++) {
        __syncthreads();
        if ((tn >> 2) == half) {
            int cl = cb - half * 32;   // 0..24
#pragma unroll
            for (int c = 0; c < 8; c++)
#pragma unroll
                for (int i = 0; i < 4; i++)
                    Ast[(cl + c) * APAD2 + rb + i] = t[i][c];
        }
#pragma unroll
        for (int i = 0; i < 2; i++) {
            int slot = tid + i * 256;
            int kk = slot >> 4, f4 = (slot & 15) * 4;
            *(float4*)&Bs[kk * BPAD2 + f4] = *(const float4*)&W2l[(half * 32 + kk) * 64 + f4];
        }
        __syncthreads();
#pragma unroll 4
        for (int kk = 0; kk < 32; kk++) {
            float4 a0 = *(float4*)&Ast[kk * APAD2 + rb];
            const unsigned long long* bp = (const unsigned long long*)&Bs[kk * BPAD2 + cb];
            unsigned long long b0 = bp[0], b1r = bp[1], b2r = bp[2], b3 = bp[3];
            unsigned long long ad[4];
            ad[0] = packdup(a0.x); ad[1] = packdup(a0.y);
            ad[2] = packdup(a0.z); ad[3] = packdup(a0.w);
#pragma unroll
            for (int i = 0; i < 4; i++) {
                ffma2(z2[i][0], ad[i], b0);
                ffma2(z2[i][1], ad[i], b1r);
                ffma2(z2[i][2], ad[i], b2r);
                ffma2(z2[i][3], ad[i], b3);
            }
        }
    }

    // bias + residual + LayerNorm + store (4 rows x 8 cols per thread)
#pragma unroll
    for (int i = 0; i < 4; i++) {
        int n = nb + rb + i;
        bool valid = n < N_;
        float4 h0 = make_float4(0.f, 0.f, 0.f, 0.f), h1 = h0;
        if (valid) {
            h0 = *(const float4*)&hin[(size_t)n * 64 + cb];
            h1 = *(const float4*)&hin[(size_t)n * 64 + cb + 4];
        }
        float zz[8];
#pragma unroll
        for (int p = 0; p < 4; p++) {
            zz[2 * p]     = __uint_as_float((unsigned)(z2[i][p] & 0xffffffffull));
            zz[2 * p + 1] = __uint_as_float((unsigned)(z2[i][p] >> 32));
        }
        zz[0] += b2s[cb + 0] + h0.x; zz[1] += b2s[cb + 1] + h0.y;
        zz[2] += b2s[cb + 2] + h0.z; zz[3] += b2s[cb + 3] + h0.w;
        zz[4] += b2s[cb + 4] + h1.x; zz[5] += b2s[cb + 5] + h1.y;
        zz[6] += b2s[cb + 6] + h1.z; zz[7] += b2s[cb + 7] + h1.w;
        float s = 0.f, ss = 0.f;
#pragma unroll
        for (int q = 0; q < 8; q++) { s += zz[q]; ss += zz[q] * zz[q]; }
        // reduce across tn (lane bits 4, 3, 0)
#pragma unroll
        for (int msk = 0; msk < 3; msk++) {
            int o = (msk == 0) ? 16 : (msk == 1) ? 8 : 1;
            s  += __shfl_xor_sync(FULLMASK, s, o);
            ss += __shfl_xor_sync(FULLMASK, ss, o);
        }
        float mu = s * (1.f / 64.f);
        float var = ss * (1.f / 64.f) - mu * mu;
        float rs = rsqrtf(var + 1e-5f);
        if (valid) {
            float4 o0, o1;
            o0.x = (zz[0] - mu) * rs * gs[cb + 0] + bs2[cb + 0];
            o0.y = (zz[1] - mu) * rs * gs[cb + 1] + bs2[cb + 1];
            o0.z = (zz[2] - mu) * rs * gs[cb + 2] + bs2[cb + 2];
            o0.w = (zz[3] - mu) * rs * gs[cb + 3] + bs2[cb + 3];
            o1.x = (zz[4] - mu) * rs * gs[cb + 4] + bs2[cb + 4];
            o1.y = (zz[5] - mu) * rs * gs[cb + 5] + bs2[cb + 5];
            o1.z = (zz[6] - mu) * rs * gs[cb + 6] + bs2[cb + 6];
            o1.w = (zz[7] - mu) * rs * gs[cb + 7] + bs2[cb + 7];
            *(float4*)&hout[(size_t)n * 64 + cb]     = o0;
            *(float4*)&hout[(size_t)n * 64 + cb + 4] = o1;
        }
    }
}

// ---------------- host launcher --------------------------------------------
extern "C" void kernel_launch(void* const* d_in, const int* in_sizes, int n_in,
                              void* d_out, int out_size)
{
    const float* x    = (const float*)d_in[0];
    const int*   ei   = (const int*)d_in[1];
    const float* ew   = (const float*)d_in[2];
    const float* gatW = (const float*)d_in[3];
    const float* asrc = (const float*)d_in[4];
    const float* adst = (const float*)d_in[5];
    const float* gbias= (const float*)d_in[6];
    const float* W1   = (const float*)d_in[7];
    const float* b1   = (const float*)d_in[8];
    const float* W2   = (const float*)d_in[9];
    const float* b2   = (const float*)d_in[10];
    const float* lng  = (const float*)d_in[11];
    const float* lnb  = (const float*)d_in[12];
    float* out = (float*)d_out;

    int aggblk = (SEG_ / 2 * 32 + 255) / 256;   // 12500

    setup_kernel<<<L_ + 17 + (SEG_ / 4 + 255) / 256, 256>>>(gatW, asrc, adst, W1, b1, gbias); // 0
    logits_ell_kernel<<<LOGITS_BLKS + ELL_BLKS, 256>>>(x, ei, ew);         // 1
    agg_kernel<<<aggblk, 256>>>(x, 0);                                     // 2
    mlp_kernel<<<(N_ + 127) / 128, 256>>>(x, W2, b2, lng, lnb, out, 0);    // 3  <- profiled
    logits_kernel<<<LOGITS_BLKS, 256>>>(1);                                // 4
    agg_kernel<<<aggblk, 256>>>(x, 1);                                     // 5
    mlp_kernel<<<(N_ + 127) / 128, 256>>>(x, W2, b2, lng, lnb, out, 1);    // 6
}

// round 16
// speedup vs baseline: 1.0355x; 1.0355x over previous
#include <cuda_runtime.h>
#include <math.h>

#define FULLMASK 0xffffffffu

constexpr int N_ = 50000;
constexpr int E_ = 400000;
constexpr int R_ = 4;
constexpr int HC_ = 128;   // H*C
constexpr int D_ = 64;     // IN == HID
constexpr int L_ = 2;
constexpr int K1_ = D_ + R_ * HC_;  // 576
constexpr int SEG_ = R_ * N_;       // 200000 segments
constexpr int CAP_ = 32;            // ELL capacity (deg ~ Poisson(4); P(>=32) ~ 1e-19)
constexpr int LOGITS_BLKS = (N_ + 63) / 64;        // 782
constexpr int ELL_BLKS = (E_ + 255) / 256;         // 1563
constexpr int NKT_ = 36;            // K1/16 k-tiles

// ---------------- scratch (device globals) ---------------------------------
__device__ int g_ellcnt[SEG_];          // zero-init at load; re-zeroed by setup
__device__ int g_ell[CAP_][SEG_];       // transposed ELL adjacency

__device__ float g_es[R_][N_][2];       // per-node source logits, per head
__device__ float g_ed[R_][N_][2];       // per-node dest logits, per head
__device__ float g_aggx[R_][N_][HC_];   // normalized alpha-weighted x, [h*64+k]
__device__ float g_hbuf[N_][D_];        // inter-layer features
__device__ float g_va[L_][2][R_][2][D_];  // folded W@a_{src,dst}
__device__ float g_W1f[L_][K1_][D_];    // MLP W1 with GAT W folded in
__device__ float g_b1f[L_][D_];         // b1 with gat_bias folded in

__device__ __forceinline__ float lrelu(float x) { return x > 0.f ? x : 0.2f * x; }

// packed 2xfp32 FMA (sm_100+): d = a*b + d elementwise on {lo,hi}
__device__ __forceinline__ void ffma2(unsigned long long& d,
                                      unsigned long long a, unsigned long long b) {
    asm("fma.rn.f32x2 %0, %1, %2, %3;" : "=l"(d) : "l"(a), "l"(b), "l"(d));
}
__device__ __forceinline__ unsigned long long packdup(float a) {
    unsigned long long d;
    unsigned int u = __float_as_uint(a);
    asm("mov.b64 %0, {%1, %1};" : "=l"(d) : "r"(u));
    return d;
}
__device__ __forceinline__ unsigned int s2u(const void* p) {
    return (unsigned int)__cvta_generic_to_shared(p);
}
__device__ __forceinline__ void cpasync16(unsigned int dst, const void* src, int sz) {
    asm volatile("cp.async.cg.shared.global [%0], [%1], 16, %2;"
                 :: "r"(dst), "l"(src), "r"(sz));
}
#define CP_COMMIT() asm volatile("cp.async.commit_group;" ::: "memory")
#define CP_WAIT1()  asm volatile("cp.async.wait_group 1;" ::: "memory")
#define CP_WAIT0()  asm volatile("cp.async.wait_group 0;" ::: "memory")

// ================= merged one-time setup ====================================
__global__ __launch_bounds__(256) void setup_kernel(
    const float* __restrict__ gatW, const float* __restrict__ asrc,
    const float* __restrict__ adst, const float* __restrict__ W1,
    const float* __restrict__ b1, const float* __restrict__ gbias)
{
    __shared__ float Wt[64][65];   // [k][c]
    __shared__ float W1t[64][64];  // [c][j]
    int b = blockIdx.x;
    int tid = threadIdx.x;

    if (b == 0) {
#pragma unroll
        for (int it = 0; it < 4; it++) {
            int t = tid + it * 256;
            int k = t & 63;
            int h = (t >> 6) & 1;
            int r = (t >> 7) & 3;
            int l = t >> 9;
            const float* Wrow = gatW + (((size_t)(l * R_ + r) * 64 + k) * 128) + h * 64;
            const float* as = asrc + ((l * R_ + r) * 2 + h) * 64;
            const float* ad = adst + ((l * R_ + r) * 2 + h) * 64;
            float ss = 0.f, ds = 0.f;
#pragma unroll 16
            for (int c = 0; c < 64; c++) { ss += Wrow[c] * as[c]; ds += Wrow[c] * ad[c]; }
            g_va[l][0][r][h][k] = ss;
            g_va[l][1][r][h][k] = ds;
        }
    } else if (b <= L_) {
        int l = b - 1;
        for (int i = tid; i < 64 * 64 / 4; i += 256)
            ((float4*)&g_W1f[l][0][0])[i] = ((const float4*)&W1[(size_t)l * K1_ * 64])[i];
        if (tid < 64) {
            float bb = b1[l * 64 + tid];
            for (int row = 0; row < 512; row++) {
                int r = row >> 7, idx = row & 127;
                bb += gbias[(l * R_ + r) * HC_ + idx] *
                      W1[((size_t)l * K1_ + 64 + row) * 64 + tid];
            }
            g_b1f[l][tid] = bb;
        }
    } else if (b <= L_ + 16) {
        int sub = b - 3;
        int l = sub >> 3, r = (sub >> 1) & 3, h = sub & 1;
#pragma unroll
        for (int i = 0; i < 4; i++) {
            int s = tid + i * 256;
            int k = s >> 4, c4 = (s & 15) * 4;
            float4 wv = *(const float4*)&gatW[((size_t)(l * R_ + r) * 64 + k) * 128 + h * 64 + c4];
            Wt[k][c4] = wv.x; Wt[k][c4 + 1] = wv.y; Wt[k][c4 + 2] = wv.z; Wt[k][c4 + 3] = wv.w;
            int c = s >> 4, j4 = (s & 15) * 4;
            *(float4*)&W1t[c][j4] =
                *(const float4*)&W1[((size_t)l * K1_ + 64 + r * 128 + h * 64 + c) * 64 + j4];
        }
        __syncthreads();
        int j4 = (tid & 15) * 4;
        int kb = tid >> 4;
#pragma unroll
        for (int kk = 0; kk < 4; kk++) {
            int k = kb + kk * 16;
            float a0 = 0.f, a1 = 0.f, a2 = 0.f, a3 = 0.f;
#pragma unroll 16
            for (int c = 0; c < 64; c++) {
                float a = Wt[k][c];
                float4 wv = *(float4*)&W1t[c][j4];
                a0 += a * wv.x; a1 += a * wv.y; a2 += a * wv.z; a3 += a * wv.w;
            }
            *(float4*)&g_W1f[l][64 + r * 128 + h * 64 + k][j4] = make_float4(a0, a1, a2, a3);
        }
    } else {
        int i4 = (b - (L_ + 17)) * 256 + tid;
        if (i4 < SEG_ / 4) ((int4*)g_ellcnt)[i4] = make_int4(0, 0, 0, 0);
    }
}

// ================= logits body =============================================
__device__ __forceinline__ void logits_body(const float* __restrict__ xcur,
                                            int layer, int blk)
{
    __shared__ float xs[64][68];
    __shared__ float vas[16][68];
    int tid = threadIdx.x;
    int nb = blk * 64;
#pragma unroll
    for (int i = 0; i < 4; i++) {
        int s = tid + i * 256;
        int row = s >> 4, c4 = (s & 15) * 4;
        int n = nb + row;
        float4 v = (n < N_) ? *(const float4*)&xcur[(size_t)n * 64 + c4]
                            : make_float4(0.f, 0.f, 0.f, 0.f);
        xs[row][c4] = v.x; xs[row][c4 + 1] = v.y; xs[row][c4 + 2] = v.z; xs[row][c4 + 3] = v.w;
    }
    {
        int o = tid >> 4, c4 = (tid & 15) * 4;
        int which = o >> 3, oo = o & 7;
        int r = oo >> 1, h = oo & 1;
        float4 v = *(const float4*)&g_va[layer][which][r][h][c4];
        vas[o][c4] = v.x; vas[o][c4 + 1] = v.y; vas[o][c4 + 2] = v.z; vas[o][c4 + 3] = v.w;
    }
    __syncthreads();

    int o = tid & 15;
    int n0 = tid >> 4;
    float s0 = 0.f, s1 = 0.f, s2 = 0.f, s3 = 0.f;
#pragma unroll
    for (int k4 = 0; k4 < 64; k4 += 4) {
        float4 va = *(float4*)&vas[o][k4];
        float4 a = *(float4*)&xs[n0][k4];
        float4 b = *(float4*)&xs[n0 + 16][k4];
        float4 c = *(float4*)&xs[n0 + 32][k4];
        float4 d = *(float4*)&xs[n0 + 48][k4];
        s0 += a.x * va.x + a.y * va.y + a.z * va.z + a.w * va.w;
        s1 += b.x * va.x + b.y * va.y + b.z * va.z + b.w * va.w;
        s2 += c.x * va.x + c.y * va.y + c.z * va.z + c.w * va.w;
        s3 += d.x * va.x + d.y * va.y + d.z * va.z + d.w * va.w;
    }
    int which = o >> 3, oo = o & 7;
    int r = oo >> 1, h = oo & 1;
    float sv[4] = {s0, s1, s2, s3};
#pragma unroll
    for (int i = 0; i < 4; i++) {
        int n = nb + n0 + i * 16;
        if (n < N_) {
            if (which == 0) g_es[r][n][h] = sv[i];
            else            g_ed[r][n][h] = sv[i];
        }
    }
}

// ================= fused: logits layer 0 + ELL build =======================
__global__ __launch_bounds__(256) void logits_ell_kernel(
    const float* __restrict__ x, const int* __restrict__ ei,
    const float* __restrict__ ew)
{
    if (blockIdx.x < LOGITS_BLKS) {
        logits_body(x, 0, blockIdx.x);
    } else {
        int e = (blockIdx.x - LOGITS_BLKS) * 256 + threadIdx.x;
        if (e >= E_) return;
        float w = ew[e];
        if (w == 0.f) return;
        int s = ei[e], d = ei[E_ + e];
        int rf = (w > 0.f) ? 0 : 2;
        int seg0 = rf * N_ + d;
        int p0 = atomicAdd(&g_ellcnt[seg0], 1);
        if (p0 < CAP_) g_ell[p0][seg0] = s;
        int seg1 = (rf + 1) * N_ + s;
        int p1 = atomicAdd(&g_ellcnt[seg1], 1);
        if (p1 < CAP_) g_ell[p1][seg1] = d;
    }
}

__global__ __launch_bounds__(256) void logits_kernel(int layer)
{
    logits_body(&g_hbuf[0][0], layer, blockIdx.x);
}

// ================= per-layer: ELL softmax-aggregate (v5) ===================
__global__ __launch_bounds__(256) void agg_kernel(const float* __restrict__ xin, int layer)
{
    const float* xcur = layer ? &g_hbuf[0][0] : xin;
    int warp = (blockIdx.x * 256 + threadIdx.x) >> 5;
    int lane = threadIdx.x & 31;
    int li = lane & 15;
    int seg = warp * 2 + (lane >> 4);   // SEG_ % 2 == 0
    if (seg >= SEG_) return;
    int r = seg / N_;
    int n = seg - r * N_;

    int deg = __ldg(&g_ellcnt[seg]);
    deg = deg < CAP_ ? deg : CAP_;

    float2 ed2 = *(const float2*)&g_ed[r][n][0];
    float2 es2 = *(const float2*)&g_es[r][n][0];
    float p0 = __expf(lrelu(es2.x + ed2.x));
    float p1 = __expf(lrelu(es2.y + ed2.y));
    float4 xv = *(const float4*)&xcur[(size_t)n * 64 + li * 4];
    float den0 = p0, den1 = p1;
    float4 A0 = make_float4(p0 * xv.x, p0 * xv.y, p0 * xv.z, p0 * xv.w);
    float4 A1 = make_float4(p1 * xv.x, p1 * xv.y, p1 * xv.z, p1 * xv.w);

    int dmax = deg;
#pragma unroll
    for (int o = 16; o; o >>= 1) {
        int y = __shfl_xor_sync(FULLMASK, dmax, o);
        dmax = dmax > y ? dmax : y;
    }
#pragma unroll 4
    for (int it = 0; it < dmax; it++) {
        int slot = it < deg ? it : 0;
        float msk = it < deg ? 1.f : 0.f;
        int src = __ldg(&g_ell[slot][seg]);
        float2 e2 = *(const float2*)&g_es[r][src][0];
        float pe0 = msk * __expf(lrelu(e2.x + ed2.x));
        float pe1 = msk * __expf(lrelu(e2.y + ed2.y));
        den0 += pe0; den1 += pe1;
        float4 sv = *(const float4*)&xcur[(size_t)src * 64 + li * 4];
        A0.x += pe0 * sv.x; A0.y += pe0 * sv.y; A0.z += pe0 * sv.z; A0.w += pe0 * sv.w;
        A1.x += pe1 * sv.x; A1.y += pe1 * sv.y; A1.z += pe1 * sv.z; A1.w += pe1 * sv.w;
    }
    float i0 = 1.f / den0, i1 = 1.f / den1;
    *(float4*)&g_aggx[r][n][li * 4] =
        make_float4(A0.x * i0, A0.y * i0, A0.z * i0, A0.w * i0);
    *(float4*)&g_aggx[r][n][64 + li * 4] =
        make_float4(A1.x * i1, A1.y * i1, A1.z * i1, A1.w * i1);
}

// ================= fused MLP + residual + LayerNorm (v4b: cp.async pipe) ===
// 256 threads, tile 128 rows x 64 cols, K-tiles of 16, double-buffered
// cp.async fills. FIX vs v4: B fills cover all 16 chunks per row.
__global__ __launch_bounds__(256, 2) void mlp_kernel(
    const float* __restrict__ xin,
    const float* __restrict__ W2, const float* __restrict__ b2,
    const float* __restrict__ lng, const float* __restrict__ lnb,
    float* __restrict__ dout, int layer)
{
    __shared__ float Asb[2][128 * 16];   // 8 KB each; [row][swizzled k]
    __shared__ float Bsb[2][16 * 72];    // 4.6 KB each; [kk][col], pad 72
    __shared__ float b1s[64], b2s[64], gs[64], bs2[64];

    int tid = threadIdx.x;
    const float* hin = layer ? &g_hbuf[0][0] : xin;
    float* hout = (layer == L_ - 1) ? dout : &g_hbuf[0][0];

    if (tid < 64) {
        b1s[tid] = g_b1f[layer][tid];
        b2s[tid] = b2[layer * 64 + tid];
        gs[tid]  = lng[layer * 64 + tid];
        bs2[tid] = lnb[layer * 64 + tid];
    }

    int nb = blockIdx.x * 128;
    int lane = tid & 31, warp = tid >> 5;
    int tn = (((lane >> 3) & 3) << 1) | (lane & 1);   // 0..7 col group
    int tmw = (lane >> 1) & 3;
    int tm = warp * 4 + tmw;                           // 0..31 row group
    int rb = tm * 4;
    int cb = tn * 8;

    unsigned int asbA[2] = { s2u(&Asb[0][0]), s2u(&Asb[1][0]) };
    unsigned int bsbA[2] = { s2u(&Bsb[0][0]), s2u(&Bsb[1][0]) };
    const float* W1l = &g_W1f[layer][0][0];

    // swizzled column offsets (in floats) for chunk c: ((c ^ tmw) << 2)
    int co2[8];
#pragma unroll
    for (int c = 0; c < 8; c++) co2[c] = ((c ^ tmw) << 2);

    // A-fill thread mapping: 2 chunks per thread (512 chunks total)
    int frow0 = tid >> 2, fch0 = tid & 3;              // slots 0..255
    int frow1 = (tid + 256) >> 2, fch1 = tid & 3;      // slots 256..511
    // B-fill mapping: 256 chunks (16 rows x 16 chunks), 1 per thread
    int bkk = tid >> 4, bch = tid & 15;

    // ---- fill tile kt into buffer bi (cp.async, no commit) ----
    auto fill_tile = [&](int kt, int bi) {
        const float* src; int stride, off;
        if (kt < 4) { src = hin; stride = 64; off = kt * 16; }
        else {
            int k0 = kt * 16 - 64;
            int rr = k0 >> 7; off = k0 & 127;
            src = &g_aggx[rr][0][0]; stride = 128;
        }
        {
            int n = nb + frow0;
            int nc = n < N_ ? n : N_ - 1;
            int sw = fch0 ^ ((frow0 >> 2) & 3);
            cpasync16(asbA[bi] + frow0 * 64 + sw * 16,
                      src + (size_t)nc * stride + off + fch0 * 4, n < N_ ? 16 : 0);
        }
        {
            int n = nb + frow1;
            int nc = n < N_ ? n : N_ - 1;
            int sw = fch1 ^ ((frow1 >> 2) & 3);
            cpasync16(asbA[bi] + frow1 * 64 + sw * 16,
                      src + (size_t)nc * stride + off + fch1 * 4, n < N_ ? 16 : 0);
        }
        // B tile: 16 rows x 64 cols = 256 chunks, one per thread (FIX)
        cpasync16(bsbA[bi] + bkk * 288 + bch * 16,
                  W1l + (size_t)(kt * 16 + bkk) * 64 + bch * 4, 16);
    };

    unsigned long long acc2[4][4];
#pragma unroll
    for (int i = 0; i < 4; i++)
#pragma unroll
        for (int p = 0; p < 4; p++) acc2[i][p] = 0ull;

    fill_tile(0, 0);
    CP_COMMIT();

    for (int kt = 0; kt < NKT_; kt++) {
        int nx = kt + 1;
        if (nx < NKT_) fill_tile(nx, nx & 1);
        CP_COMMIT();
        CP_WAIT1();
        __syncthreads();

        const float* Ab = &Asb[kt & 1][0];
        const float* Bb = &Bsb[kt & 1][0];
#pragma unroll
        for (int kk = 0; kk < 16; kk++) {
            int c = kk >> 2;
            float a0 = Ab[(rb + 0) * 16 + co2[c] + (kk & 3)];
            float a1 = Ab[(rb + 1) * 16 + co2[c] + (kk & 3)];
            float a2 = Ab[(rb + 2) * 16 + co2[c] + (kk & 3)];
            float a3 = Ab[(rb + 3) * 16 + co2[c] + (kk & 3)];
            const unsigned long long* bp = (const unsigned long long*)&Bb[kk * 72 + cb];
            unsigned long long b0 = bp[0], b1r = bp[1], b2r = bp[2], b3 = bp[3];
            unsigned long long ad[4] = { packdup(a0), packdup(a1), packdup(a2), packdup(a3) };
#pragma unroll
            for (int i = 0; i < 4; i++) {
                ffma2(acc2[i][0], ad[i], b0);
                ffma2(acc2[i][1], ad[i], b1r);
                ffma2(acc2[i][2], ad[i], b2r);
                ffma2(acc2[i][3], ad[i], b3);
            }
        }
        __syncthreads();
    }
    CP_WAIT0();

    // unpack + bias + tanh -> t[4 rows][8 cols]
    float t[4][8];
#pragma unroll
    for (int i = 0; i < 4; i++)
#pragma unroll
        for (int p = 0; p < 4; p++) {
            float lo = __uint_as_float((unsigned)(acc2[i][p] & 0xffffffffull));
            float hi = __uint_as_float((unsigned)(acc2[i][p] >> 32));
            t[i][2 * p]     = tanhf(lo + b1s[cb + 2 * p]);
            t[i][2 * p + 1] = tanhf(hi + b1s[cb + 2 * p + 1]);
        }

    // GEMM2: K=64 in two 32-k halves. Stage t into Asb (flat 128x32, swizzled),
    // B2 via cp.async into Bsb (flat 32x72).
    const float* W2l = W2 + (size_t)layer * 64 * 64;
    float* At = &Asb[0][0];      // 128 rows x 32 k (both buffers)
    float* B2s = &Bsb[0][0];     // 32 kk x 72 (both buffers)
    unsigned int b2A = bsbA[0];

    unsigned long long z2[4][4];
#pragma unroll
    for (int i = 0; i < 4; i++)
#pragma unroll
        for (int p = 0; p < 4; p++) z2[i][p] = 0ull;

    for (int half = 0; half < 2; half++) {
        __syncthreads();
        if ((tn >> 2) == half) {
            int kl = cb - half * 32;   // 0,8,16,24
#pragma unroll
            for (int c = 0; c < 8; c++) {
                int k = kl + c;
                int sw = (((k >> 2) ^ tmw) << 2) + (k & 3);
#pragma unroll
                for (int i = 0; i < 4; i++)
                    At[(rb + i) * 32 + sw] = t[i][c];
            }
        }
        // B2: 32 rows x 16 chunks = 512 chunks, 2 per thread (FIX)
#pragma unroll
        for (int i = 0; i < 2; i++) {
            int slot = tid + i * 256;
            int kkr = slot >> 4, ch = slot & 15;
            cpasync16(b2A + kkr * 288 + ch * 16,
                      W2l + (size_t)(half * 32 + kkr) * 64 + ch * 4, 16);
        }
        CP_COMMIT();
        CP_WAIT0();
        __syncthreads();
#pragma unroll 8
        for (int kk = 0; kk < 32; kk++) {
            int c = kk >> 2;
            float a0 = At[(rb + 0) * 32 + co2[c] + (kk & 3)];
            float a1 = At[(rb + 1) * 32 + co2[c] + (kk & 3)];
            float a2 = At[(rb + 2) * 32 + co2[c] + (kk & 3)];
            float a3 = At[(rb + 3) * 32 + co2[c] + (kk & 3)];
            const unsigned long long* bp = (const unsigned long long*)&B2s[kk * 72 + cb];
            unsigned long long b0 = bp[0], b1r = bp[1], b2r = bp[2], b3 = bp[3];
            unsigned long long ad[4] = { packdup(a0), packdup(a1), packdup(a2), packdup(a3) };
#pragma unroll
            for (int i = 0; i < 4; i++) {
                ffma2(z2[i][0], ad[i], b0);
                ffma2(z2[i][1], ad[i], b1r);
                ffma2(z2[i][2], ad[i], b2r);
                ffma2(z2[i][3], ad[i], b3);
            }
        }
    }

    // bias + residual + LayerNorm + store (4 rows x 8 cols per thread)
#pragma unroll
    for (int i = 0; i < 4; i++) {
        int n = nb + rb + i;
        bool valid = n < N_;
        float4 h0 = make_float4(0.f, 0.f, 0.f, 0.f), h1 = h0;
        if (valid) {
            h0 = *(const float4*)&hin[(size_t)n * 64 + cb];
            h1 = *(const float4*)&hin[(size_t)n * 64 + cb + 4];
        }
        float zz[8];
#pragma unroll
        for (int p = 0; p < 4; p++) {
            zz[2 * p]     = __uint_as_float((unsigned)(z2[i][p] & 0xffffffffull));
            zz[2 * p + 1] = __uint_as_float((unsigned)(z2[i][p] >> 32));
        }
        zz[0] += b2s[cb + 0] + h0.x; zz[1] += b2s[cb + 1] + h0.y;
        zz[2] += b2s[cb + 2] + h0.z; zz[3] += b2s[cb + 3] + h0.w;
        zz[4] += b2s[cb + 4] + h1.x; zz[5] += b2s[cb + 5] + h1.y;
        zz[6] += b2s[cb + 6] + h1.z; zz[7] += b2s[cb + 7] + h1.w;
        float s = 0.f, ss = 0.f;
#pragma unroll
        for (int q = 0; q < 8; q++) { s += zz[q]; ss += zz[q] * zz[q]; }
        // reduce across tn (lane bits 4, 3, 0)
#pragma unroll
        for (int msk = 0; msk < 3; msk++) {
            int o = (msk == 0) ? 16 : (msk == 1) ? 8 : 1;
            s  += __shfl_xor_sync(FULLMASK, s, o);
            ss += __shfl_xor_sync(FULLMASK, ss, o);
        }
        float mu = s * (1.f / 64.f);
        float var = ss * (1.f / 64.f) - mu * mu;
        float rs = rsqrtf(var + 1e-5f);
        if (valid) {
            float4 o0, o1;
            o0.x = (zz[0] - mu) * rs * gs[cb + 0] + bs2[cb + 0];
            o0.y = (zz[1] - mu) * rs * gs[cb + 1] + bs2[cb + 1];
            o0.z = (zz[2] - mu) * rs * gs[cb + 2] + bs2[cb + 2];
            o0.w = (zz[3] - mu) * rs * gs[cb + 3] + bs2[cb + 3];
            o1.x = (zz[4] - mu) * rs * gs[cb + 4] + bs2[cb + 4];
            o1.y = (zz[5] - mu) * rs * gs[cb + 5] + bs2[cb + 5];
            o1.z = (zz[6] - mu) * rs * gs[cb + 6] + bs2[cb + 6];
            o1.w = (zz[7] - mu) * rs * gs[cb + 7] + bs2[cb + 7];
            *(float4*)&hout[(size_t)n * 64 + cb]     = o0;
            *(float4*)&hout[(size_t)n * 64 + cb + 4] = o1;
        }
    }
}

// ---------------- host launcher --------------------------------------------
extern "C" void kernel_launch(void* const* d_in, const int* in_sizes, int n_in,
                              void* d_out, int out_size)
{
    const float* x    = (const float*)d_in[0];
    const int*   ei   = (const int*)d_in[1];
    const float* ew   = (const float*)d_in[2];
    const float* gatW = (const float*)d_in[3];
    const float* asrc = (const float*)d_in[4];
    const float* adst = (const float*)d_in[5];
    const float* gbias= (const float*)d_in[6];
    const float* W1   = (const float*)d_in[7];
    const float* b1   = (const float*)d_in[8];
    const float* W2   = (const float*)d_in[9];
    const float* b2   = (const float*)d_in[10];
    const float* lng  = (const float*)d_in[11];
    const float* lnb  = (const float*)d_in[12];
    float* out = (float*)d_out;

    int aggblk = (SEG_ / 2 * 32 + 255) / 256;   // 12500

    setup_kernel<<<L_ + 17 + (SEG_ / 4 + 255) / 256, 256>>>(gatW, asrc, adst, W1, b1, gbias); // 0
    logits_ell_kernel<<<LOGITS_BLKS + ELL_BLKS, 256>>>(x, ei, ew);         // 1
    agg_kernel<<<aggblk, 256>>>(x, 0);                                     // 2
    mlp_kernel<<<(N_ + 127) / 128, 256>>>(x, W2, b2, lng, lnb, out, 0);    // 3  <- profiled
    logits_kernel<<<LOGITS_BLKS, 256>>>(1);                                // 4
    agg_kernel<<<aggblk, 256>>>(x, 1);                                     // 5
    mlp_kernel<<<(N_ + 127) / 128, 256>>>(x, W2, b2, lng, lnb, out, 1);    // 6
}